// round 15
// baseline (speedup 1.0000x reference)
#include <cuda_runtime.h>
#include <math.h>
#include <stdint.h>

#define BB 2
#define NTOK 4096
#define DM 768
#define NH 12
#define DHEAD 64
#define NBLK 64
#define BS 64
#define FFD 3072
#define NL 2
#define RR 3
#define KH_DD (DM / 2)    // 384
#define KH_FF (FFD / 2)   // 1536
#define GS 2304           // fused qkv width
#define PQS (GS / 2)      // 1152 packed row stride

// packed weight layout per layer (uint32 words)
#define QKV_WORDS (GS * KH_DD)
#define WO_OFF    QKV_WORDS
#define WI_OFF    (WO_OFF + DM * KH_DD)
#define WD_OFF    (WI_OFF + FFD * KH_DD)
#define LOFF      (WD_OFF + DM * KH_FF)

// attention smem layout (u32 words): Q hi/lo at 0/2048; KV buffers at 4096 + buf*8704
// within a KV buffer: KH +0, KL +2048, VH +4096, VL +6400 (size 8704)
#define AQH 0
#define AQL 2048
#define AKV0 4096
#define KVSZ 8704

// ---------------- scratch ----------------
__device__ float g_x[BB * NTOK * DM];
__device__ float g_t[BB * NTOK * DM];
__device__ float g_t2[BB * NTOK * DM];
__device__ float g_a[BB * NTOK * DM];
__device__ float g_part[BB * 32];
__device__ float g_bqkv[2 * GS];
__device__ float g_zb[DM];                      // zero bias (.bss)
__device__ uint32_t g_pqh[BB * NTOK * PQS];
__device__ uint32_t g_pql[BB * NTOK * PQS];
__device__ uint32_t g_pxh[BB * NTOK * KH_DD];
__device__ uint32_t g_pxl[BB * NTOK * KH_DD];
__device__ uint32_t g_pch[BB * NTOK * KH_DD];
__device__ uint32_t g_pcl[BB * NTOK * KH_DD];
__device__ uint32_t g_phh[BB * NTOK * KH_FF];
__device__ uint32_t g_phl[BB * NTOK * KH_FF];
__device__ uint32_t g_wh[2 * LOFF];
__device__ uint32_t g_wl[2 * LOFF];
__device__ float g_eo[2 * NH * BB * 8 * 64 * 64];
__device__ float g_em[2 * NH * BB * 8 * 64];
__device__ float g_el[2 * NH * BB * 8 * 64];

// ---------------- helpers ----------------
__device__ __forceinline__ uint32_t f2bf(float x) {
    uint32_t u = __float_as_uint(x);
    return (u + 0x7FFFu + ((u >> 16) & 1u)) >> 16;
}
__device__ __forceinline__ float bf2f(uint32_t h) { return __uint_as_float(h << 16); }
__device__ __forceinline__ void pack2(float a, float b, uint32_t& hi, uint32_t& lo) {
    uint32_t h0 = f2bf(a), h1 = f2bf(b);
    hi = h0 | (h1 << 16);
    lo = f2bf(a - bf2f(h0)) | (f2bf(b - bf2f(h1)) << 16);
}
__device__ __forceinline__ uint32_t smem_u32(const void* p) {
    uint32_t a;
    asm("{ .reg .u64 t; cvta.to.shared.u64 t, %1; cvt.u32.u64 %0, t; }" : "=r"(a) : "l"(p));
    return a;
}
__device__ __forceinline__ void cp16(uint32_t saddr, const void* g) {
    asm volatile("cp.async.ca.shared.global [%0], [%1], 16;" :: "r"(saddr), "l"(g));
}
#define CP_COMMIT() asm volatile("cp.async.commit_group;" ::: "memory")
#define CP_WAIT1()  asm volatile("cp.async.wait_group 1;" ::: "memory")
#define CP_WAIT0()  asm volatile("cp.async.wait_group 0;" ::: "memory")

__device__ __forceinline__ void ldmat_x4(uint32_t* r, uint32_t saddr) {
    asm volatile("ldmatrix.sync.aligned.m8n8.x4.shared.b16 {%0,%1,%2,%3}, [%4];"
                 : "=r"(r[0]), "=r"(r[1]), "=r"(r[2]), "=r"(r[3]) : "r"(saddr));
}
__device__ __forceinline__ void ldmat_x4_t(uint32_t* r, uint32_t saddr) {
    asm volatile("ldmatrix.sync.aligned.m8n8.x4.trans.shared.b16 {%0,%1,%2,%3}, [%4];"
                 : "=r"(r[0]), "=r"(r[1]), "=r"(r[2]), "=r"(r[3]) : "r"(saddr));
}
__device__ __forceinline__ void mma_bf16(float* c, const uint32_t* a, const uint32_t* b) {
    asm volatile(
        "mma.sync.aligned.m16n8k16.row.col.f32.bf16.bf16.f32 "
        "{%0,%1,%2,%3}, {%4,%5,%6,%7}, {%8,%9}, {%0,%1,%2,%3};"
        : "+f"(c[0]), "+f"(c[1]), "+f"(c[2]), "+f"(c[3])
        : "r"(a[0]), "r"(a[1]), "r"(a[2]), "r"(a[3]), "r"(b[0]), "r"(b[1]));
}

// ---------------- batched weight packs ----------------
__device__ __forceinline__ void pack_tile(
    const float* __restrict__ W, uint32_t* __restrict__ hi, uint32_t* __restrict__ lo,
    int K, int N, int Kh, int k0, int n0, size_t dbase)
{
    __shared__ float tile[64][33];
    int t = threadIdx.x;
    for (int i = t; i < 64 * 32; i += 256) {
        int r = i >> 5, c = i & 31;
        tile[r][c] = W[(size_t)(k0 + r) * N + n0 + c];
    }
    __syncthreads();
    for (int i = t; i < 32 * 32; i += 256) {
        int n = i >> 5, kp = i & 31;
        size_t o = dbase + (size_t)(n0 + n) * Kh + (k0 >> 1) + kp;
        pack2(tile[kp * 2][n], tile[kp * 2 + 1][n], hi[o], lo[o]);
    }
}

__global__ __launch_bounds__(256) void pack_wA_kernel(
    const float* __restrict__ Wq, const float* __restrict__ Wk,
    const float* __restrict__ Wv, const float* __restrict__ Wo,
    uint32_t* __restrict__ hi, uint32_t* __restrict__ lo)
{
    int z = blockIdx.z, layer = z >> 2, which = z & 3;
    const float* W = (which == 0 ? Wq : which == 1 ? Wk : which == 2 ? Wv : Wo)
                     + (size_t)layer * DM * DM;
    size_t dbase = (size_t)layer * LOFF +
                   (which < 3 ? (size_t)which * DM * KH_DD : (size_t)WO_OFF);
    pack_tile(W, hi, lo, DM, DM, KH_DD, blockIdx.y * 64, blockIdx.x * 32, dbase);
}

__global__ __launch_bounds__(256) void pack_wB_kernel(
    const float* __restrict__ Wi, uint32_t* __restrict__ hi, uint32_t* __restrict__ lo)
{
    int layer = blockIdx.z;
    pack_tile(Wi + (size_t)layer * DM * FFD, hi, lo, DM, FFD, KH_DD,
              blockIdx.y * 64, blockIdx.x * 32, (size_t)layer * LOFF + WI_OFF);
}

__global__ __launch_bounds__(256) void pack_wC_kernel(
    const float* __restrict__ Wd, uint32_t* __restrict__ hi, uint32_t* __restrict__ lo)
{
    int layer = blockIdx.z;
    pack_tile(Wd + (size_t)layer * FFD * DM, hi, lo, FFD, DM, KH_FF,
              blockIdx.y * 64, blockIdx.x * 32, (size_t)layer * LOFF + WD_OFF);
}

__global__ void concat_bias_kernel(const float* __restrict__ a, const float* __restrict__ b,
                                   const float* __restrict__ c, float* __restrict__ o)
{
    int t = blockIdx.x * 256 + threadIdx.x;
    if (t >= 2 * GS) return;
    int l = t / GS, j = t - l * GS;
    float v;
    if (j < DM) v = a[l * DM + j];
    else if (j < 2 * DM) v = b[l * DM + j - DM];
    else v = c[l * DM + j - 2 * DM];
    o[t] = v;
}

// ---------------- block reduce (final head only) ----------------
__device__ __forceinline__ void block_reduce2(float& s, float& s2) {
#pragma unroll
    for (int off = 16; off > 0; off >>= 1) {
        s  += __shfl_down_sync(0xffffffffu, s, off);
        s2 += __shfl_down_sync(0xffffffffu, s2, off);
    }
    __shared__ float sh[16];
    int w = threadIdx.x >> 5, lane = threadIdx.x & 31;
    if (lane == 0) { sh[w] = s; sh[8 + w] = s2; }
    __syncthreads();
    if (threadIdx.x == 0) {
        float a = 0.f, b = 0.f;
#pragma unroll
        for (int i = 0; i < 8; i++) { a += sh[i]; b += sh[8 + i]; }
        sh[0] = a; sh[8] = b;
    }
    __syncthreads();
    s = sh[0]; s2 = sh[8];
}

// ---------------- warp-per-row LN kernels ----------------
__device__ __forceinline__ void ln_warp_finish(
    float2* v, int lane, const float* g, const float* bta,
    float* out, uint32_t* ph, uint32_t* pl, size_t rowp)
{
    float s = 0.f, s2 = 0.f;
#pragma unroll
    for (int j = 0; j < 12; j++) {
        s  += v[j].x + v[j].y;
        s2 += v[j].x * v[j].x + v[j].y * v[j].y;
    }
#pragma unroll
    for (int off = 16; off > 0; off >>= 1) {
        s  += __shfl_xor_sync(0xffffffffu, s, off);
        s2 += __shfl_xor_sync(0xffffffffu, s2, off);
    }
    float mean = s * (1.f / DM);
    float var = s2 * (1.f / DM) - mean * mean;
    float rstd = rsqrtf(var + 1e-12f);
#pragma unroll
    for (int j = 0; j < 12; j++) {
        int idx = lane + j * 32;
        float2 gg = ((const float2*)g)[idx];
        float2 bb = ((const float2*)bta)[idx];
        float a = (v[j].x - mean) * rstd * gg.x + bb.x;
        float b = (v[j].y - mean) * rstd * gg.y + bb.y;
        ((float2*)out)[rowp + idx] = make_float2(a, b);
        pack2(a, b, ph[rowp + idx], pl[rowp + idx]);
    }
}

__global__ __launch_bounds__(256) void embed_ln_kernel(
    const float* __restrict__ e, const float* __restrict__ pos,
    const float* __restrict__ tt, const float* __restrict__ g,
    const float* __restrict__ bta, float* __restrict__ out,
    uint32_t* __restrict__ ph, uint32_t* __restrict__ pl)
{
    int warp = threadIdx.x >> 5, lane = threadIdx.x & 31;
    int row = blockIdx.x * 8 + warp;
    size_t rowp = (size_t)row * 384;
    size_t posp = (size_t)(row & (NTOK - 1)) * 384;
    float2 v[12];
#pragma unroll
    for (int j = 0; j < 12; j++) {
        int idx = lane + j * 32;
        float2 a = ((const float2*)e)[rowp + idx];
        float2 p = ((const float2*)pos)[posp + idx];
        float2 q = ((const float2*)tt)[idx];
        v[j] = make_float2(a.x + p.x + q.x, a.y + p.y + q.y);
    }
    ln_warp_finish(v, lane, g, bta, out, ph, pl, rowp);
}

// out = LN(r + y1 + y2)
__global__ __launch_bounds__(256) void ln_add3_kernel(
    const float* __restrict__ r, const float* __restrict__ y1,
    const float* __restrict__ y2,
    const float* __restrict__ g, const float* __restrict__ bta,
    float* __restrict__ out, uint32_t* __restrict__ ph, uint32_t* __restrict__ pl)
{
    int warp = threadIdx.x >> 5, lane = threadIdx.x & 31;
    int row = blockIdx.x * 8 + warp;
    size_t rowp = (size_t)row * 384;
    float2 v[12];
#pragma unroll
    for (int j = 0; j < 12; j++) {
        int idx = lane + j * 32;
        float2 a = ((const float2*)r)[rowp + idx];
        float2 b = ((const float2*)y1)[rowp + idx];
        float2 c = ((const float2*)y2)[rowp + idx];
        v[j] = make_float2(a.x + b.x + c.x, a.y + b.y + c.y);
    }
    ln_warp_finish(v, lane, g, bta, out, ph, pl, rowp);
}

// ---------------- packed bf16 3-pass GEMM (2-stage pipeline + optional split-K) ----------------
template<int GELU, int PACK>
__global__ __launch_bounds__(256, 2) void mgemm_kernel(
    const uint32_t* __restrict__ Ah, const uint32_t* __restrict__ Al,
    const uint32_t* __restrict__ Bh, const uint32_t* __restrict__ Bl,
    const float* __restrict__ bias, float* __restrict__ C,
    uint32_t* __restrict__ Oh, uint32_t* __restrict__ Ol,
    const float* __restrict__ bias2, float* __restrict__ C2,
    int Kh, int kcnt, int Nn)
{
    extern __shared__ uint32_t sm[];
    uint32_t smem_addr = smem_u32(sm);
    const int RAH = 0, RAL = 2048, RBH = 4096, RBL = 6144;
    const uint32_t BUF_BYTES = 32768;

    const int t = threadIdx.x;
    const int wid = t >> 5, lane = t & 31;
    const int wr0 = (wid >> 1) * 32;
    const int wc0 = (wid & 1) * 64;
    const int lr = lane >> 2, lc = lane & 3;
    const int aRow0 = blockIdx.y * 128;
    const int bRow0 = blockIdx.x * 128;
    int kpBase = 0;
    if (blockIdx.z) { kpBase = kcnt * 16; bias = bias2; C = C2; }

    float acc[2][8][4];
#pragma unroll
    for (int i = 0; i < 2; i++)
#pragma unroll
        for (int j = 0; j < 8; j++)
#pragma unroll
            for (int q = 0; q < 4; q++) acc[i][j][q] = 0.f;

    auto ISSUE = [&](int c) {
        uint32_t sb = smem_addr + (uint32_t)(c & 1) * BUF_BYTES;
        int kp0 = kpBase + c * 16;
#pragma unroll
        for (int i = 0; i < 8; i++) {
            int reg = i >> 1;
            int f = t + (i & 1) * 256;
            int row = f >> 2, w4 = f & 3;
            int sw = (w4 ^ ((row >> 1) & 3)) << 2;
            const uint32_t* g;
            int ro;
            if (reg == 0)      { g = Ah + (size_t)(aRow0 + row) * Kh + kp0 + w4 * 4; ro = RAH; }
            else if (reg == 1) { g = Al + (size_t)(aRow0 + row) * Kh + kp0 + w4 * 4; ro = RAL; }
            else if (reg == 2) { g = Bh + (size_t)(bRow0 + row) * Kh + kp0 + w4 * 4; ro = RBH; }
            else               { g = Bl + (size_t)(bRow0 + row) * Kh + kp0 + w4 * 4; ro = RBL; }
            cp16(sb + (uint32_t)(ro + row * 16 + sw) * 4u, g);
        }
        CP_COMMIT();
    };

    uint32_t ah_[2][4], al_[2][4], bf[8][2];
    auto LDA = [&](uint32_t (&dst)[2][4], uint32_t sb, int regOff, int s) {
#pragma unroll
        for (int mt = 0; mt < 2; mt++) {
            int row = wr0 + mt * 16 + (lane & 15);
            int c4 = (2 * s + (lane >> 4)) ^ ((row >> 1) & 3);
            ldmat_x4(dst[mt], sb + (uint32_t)((regOff + row * 16 + (c4 << 2)) * 4));
        }
    };
    auto LDB = [&](uint32_t sb, int regOff, int s) {
#pragma unroll
        for (int nt0 = 0; nt0 < 8; nt0 += 2) {
            int row = wc0 + nt0 * 8 + ((lane & 16) >> 1) + (lane & 7);
            int c4 = (2 * s + ((lane & 8) >> 3)) ^ ((row >> 1) & 3);
            uint32_t regs[4];
            ldmat_x4(regs, sb + (uint32_t)((regOff + row * 16 + (c4 << 2)) * 4));
            bf[nt0][0] = regs[0]; bf[nt0][1] = regs[1];
            bf[nt0 + 1][0] = regs[2]; bf[nt0 + 1][1] = regs[3];
        }
    };
    auto MMAS = [&](uint32_t (&a)[2][4]) {
#pragma unroll
        for (int mt = 0; mt < 2; mt++)
#pragma unroll
            for (int nt = 0; nt < 8; nt++) mma_bf16(acc[mt][nt], a[mt], bf[nt]);
    };
    auto COMP = [&](int buf) {
        uint32_t sb = smem_addr + (uint32_t)buf * BUF_BYTES;
#pragma unroll
        for (int s = 0; s < 2; s++) {
            LDA(ah_, sb, RAH, s);
            LDA(al_, sb, RAL, s);
            LDB(sb, RBH, s);
            MMAS(ah_);            // hh
            MMAS(al_);            // lh
            LDB(sb, RBL, s);
            MMAS(ah_);            // hl
        }
    };

    const int nch = kcnt;
    ISSUE(0);
    if (nch > 1) ISSUE(1);
    for (int c = 0; c < nch; c++) {
        if (c + 1 < nch) { CP_WAIT1(); } else { CP_WAIT0(); }
        __syncthreads();
        COMP(c & 1);
        __syncthreads();
        if (c + 2 < nch) ISSUE(c + 2);
    }

    const int Khn = Nn >> 1;
#pragma unroll
    for (int mt = 0; mt < 2; mt++) {
        int r = blockIdx.y * 128 + wr0 + mt * 16 + lr;
#pragma unroll
        for (int nt = 0; nt < 8; nt++) {
            int cc = blockIdx.x * 128 + wc0 + nt * 8 + lc * 2;
            float b0 = bias[cc], b1 = bias[cc + 1];
            float v[4];
            v[0] = acc[mt][nt][0] + b0; v[1] = acc[mt][nt][1] + b1;
            v[2] = acc[mt][nt][2] + b0; v[3] = acc[mt][nt][3] + b1;
            if (GELU) {
#pragma unroll
                for (int q = 0; q < 4; q++) {
                    float z = 0.7978845608028654f * (v[q] + 0.044715f * v[q] * v[q] * v[q]);
                    float e = __expf(2.f * z);
                    v[q] = 0.5f * v[q] * (2.f - 2.f / (e + 1.f));
                }
            }
            if (PACK) {
                int kp = cc >> 1;
                pack2(v[0], v[1], Oh[(size_t)r * Khn + kp], Ol[(size_t)r * Khn + kp]);
                pack2(v[2], v[3], Oh[(size_t)(r + 8) * Khn + kp], Ol[(size_t)(r + 8) * Khn + kp]);
            } else {
                *(float2*)(C + (size_t)r * Nn + cc) = make_float2(v[0], v[1]);
                *(float2*)(C + (size_t)(r + 8) * Nn + cc) = make_float2(v[2], v[3]);
            }
        }
    }
}

// ---------------- attention: unified mma flash kernel, double-buffered KV ----------------
// grid.x: [0, 62) middle q-blocks (m = x+1); [62, 78) edge partials
// (idx = x-62: e = idx>>3, s0 = idx&7).
__global__ __launch_bounds__(256) void attn_mma_kernel(
    const uint32_t* __restrict__ pqh, const uint32_t* __restrict__ pql,
    const int* __restrict__ rb,
    uint32_t* __restrict__ pch, uint32_t* __restrict__ pcl,
    float* __restrict__ eo, float* __restrict__ em, float* __restrict__ el)
{
    extern __shared__ uint32_t su[];
    uint32_t sbase = smem_u32(su);
    int t = threadIdx.x, wid = t >> 5, lane = t & 31;
    int mrow0 = (wid & 3) * 16;
    int kh2 = wid >> 2;
    int kcol0 = kh2 * 32;

    int h = blockIdx.y, b = blockIdx.z;
    int x = blockIdx.x;
    bool edge = (x >= NBLK - 2);
    int m, s0 = 0, e = 0;
    if (edge) {
        int idx = x - (NBLK - 2);
        e = idx >> 3; s0 = idx & 7;
        m = e ? (NBLK - 1) : 0;
    } else m = x + 1;

    const uint32_t* qh = pqh + (size_t)(b * NTOK + m * BS) * PQS + h * 32;
    const uint32_t* ql = pql + (size_t)(b * NTOK + m * BS) * PQS + h * 32;
    const uint32_t* kbh = pqh + (size_t)b * NTOK * PQS + KH_DD + h * 32;
    const uint32_t* kbl = pql + (size_t)b * NTOK * PQS + KH_DD + h * 32;
    const uint32_t* vbh = pqh + (size_t)b * NTOK * PQS + 2 * KH_DD + h * 32;
    const uint32_t* vbl = pql + (size_t)b * NTOK * PQS + 2 * KH_DD + h * 32;

    // Q fill (once)
    for (int u = t; u < 512; u += 256) {
        int r = u >> 3, c4 = u & 7;
        uint32_t doff = (uint32_t)((r * 32 + ((c4 ^ (r & 7)) << 2)) * 4);
        cp16(sbase + (uint32_t)(AQH * 4) + doff, qh + (size_t)r * PQS + c4 * 4);
        cp16(sbase + (uint32_t)(AQL * 4) + doff, ql + (size_t)r * PQS + c4 * 4);
    }
    CP_COMMIT();

    int list[8];
    if (!edge) {
        const int* r3 = rb + (h * NBLK + m) * RR;
        list[0] = 0; list[1] = NBLK - 1;
        list[2] = m - 1; list[3] = m; list[4] = m + 1;
        list[5] = r3[0]; list[6] = r3[1]; list[7] = r3[2];
    }

    auto ISSUE_KV = [&](int step) {
        int blk = edge ? (s0 * 8 + step) : list[step];
        const uint32_t* kh = kbh + (size_t)(blk * BS) * PQS;
        const uint32_t* kl = kbl + (size_t)(blk * BS) * PQS;
        const uint32_t* vh = vbh + (size_t)(blk * BS) * PQS;
        const uint32_t* vl = vbl + (size_t)(blk * BS) * PQS;
        uint32_t kvb = sbase + (uint32_t)((AKV0 + (step & 1) * KVSZ) * 4);
        for (int u = t; u < 512; u += 256) {
            int r = u >> 3, c4 = u & 7;
            uint32_t doff = (uint32_t)((r * 32 + ((c4 ^ (r & 7)) << 2)) * 4);
            cp16(kvb + doff, kh + (size_t)r * PQS + c4 * 4);
            cp16(kvb + 2048u * 4u + doff, kl + (size_t)r * PQS + c4 * 4);
        }
        for (int u = t; u < 512; u += 256) {
            int j = u >> 3, w4 = u & 7;
            uint32_t doff = (uint32_t)((j * 36 + w4 * 4) * 4);
            cp16(kvb + 4096u * 4u + doff, vh + (size_t)j * PQS + w4 * 4);
            cp16(kvb + 6400u * 4u + doff, vl + (size_t)j * PQS + w4 * 4);
        }
        CP_COMMIT();
    };

    float o[8][4];
#pragma unroll
    for (int i = 0; i < 8; i++)
#pragma unroll
        for (int j = 0; j < 4; j++) o[i][j] = 0.f;
    float m0 = -1e30f, m8 = -1e30f, l0 = 0.f, l8 = 0.f;

    ISSUE_KV(0);
    for (int step = 0; step < 8; step++) {
        if (step + 1 < 8) { ISSUE_KV(step + 1); CP_WAIT1(); } else { CP_WAIT0(); }
        __syncthreads();
        int kvw = AKV0 + (step & 1) * KVSZ;   // u32 word base of current KV buffer

        // QK^T 3-pass
        float s[4][4];
#pragma unroll
        for (int i = 0; i < 4; i++)
#pragma unroll
            for (int j = 0; j < 4; j++) s[i][j] = 0.f;
#pragma unroll
        for (int ks = 0; ks < 4; ks++) {
            uint32_t aH[4], aL[4];
            {
                int r = mrow0 + (lane & 15);
                int c4 = (2 * ks + (lane >> 4)) ^ (r & 7);
                ldmat_x4(aH, sbase + (uint32_t)((AQH + r * 32 + (c4 << 2)) * 4));
                ldmat_x4(aL, sbase + (uint32_t)((AQL + r * 32 + (c4 << 2)) * 4));
            }
#pragma unroll
            for (int ntp = 0; ntp < 4; ntp += 2) {
                uint32_t bh[4], bl[4];
                {
                    int r = kcol0 + ntp * 8 + ((lane & 16) >> 1) + (lane & 7);
                    int c4 = (2 * ks + ((lane & 8) >> 3)) ^ (r & 7);
                    ldmat_x4(bh, sbase + (uint32_t)((kvw + r * 32 + (c4 << 2)) * 4));
                    ldmat_x4(bl, sbase + (uint32_t)((kvw + 2048 + r * 32 + (c4 << 2)) * 4));
                }
                mma_bf16(s[ntp], aH, bh);     mma_bf16(s[ntp + 1], aH, bh + 2);
                mma_bf16(s[ntp], aH, bl);     mma_bf16(s[ntp + 1], aH, bl + 2);
                mma_bf16(s[ntp], aL, bh);     mma_bf16(s[ntp + 1], aL, bh + 2);
            }
        }

        // softmax (slice-local online)
        float mx0 = -1e30f, mx8 = -1e30f;
#pragma unroll
        for (int nt = 0; nt < 4; nt++) {
#pragma unroll
            for (int j = 0; j < 4; j++) s[nt][j] *= 0.125f;
            mx0 = fmaxf(mx0, fmaxf(s[nt][0], s[nt][1]));
            mx8 = fmaxf(mx8, fmaxf(s[nt][2], s[nt][3]));
        }
        mx0 = fmaxf(mx0, __shfl_xor_sync(0xffffffffu, mx0, 1));
        mx0 = fmaxf(mx0, __shfl_xor_sync(0xffffffffu, mx0, 2));
        mx8 = fmaxf(mx8, __shfl_xor_sync(0xffffffffu, mx8, 1));
        mx8 = fmaxf(mx8, __shfl_xor_sync(0xffffffffu, mx8, 2));
        float mn0 = fmaxf(m0, mx0), mn8 = fmaxf(m8, mx8);
        float c0 = __expf(m0 - mn0), c8 = __expf(m8 - mn8);
        float ls0 = 0.f, ls8 = 0.f;
#pragma unroll
        for (int nt = 0; nt < 4; nt++) {
            s[nt][0] = __expf(s[nt][0] - mn0); ls0 += s[nt][0];
            s[nt][1] = __expf(s[nt][1] - mn0); ls0 += s[nt][1];
            s[nt][2] = __expf(s[nt][2] - mn8); ls8 += s[nt][2];
            s[nt][3] = __expf(s[nt][3] - mn8); ls8 += s[nt][3];
        }
        ls0 += __shfl_xor_sync(0xffffffffu, ls0, 1);
        ls0 += __shfl_xor_sync(0xffffffffu, ls0, 2);
        ls8 += __shfl_xor_sync(0xffffffffu, ls8, 1);
        ls8 += __shfl_xor_sync(0xffffffffu, ls8, 2);
        l0 = l0 * c0 + ls0; l8 = l8 * c8 + ls8;
        m0 = mn0; m8 = mn8;
#pragma unroll
        for (int nd = 0; nd < 8; nd++) {
            o[nd][0] *= c0; o[nd][1] *= c0;
            o[nd][2] *= c8; o[nd][3] *= c8;
        }

        // PV 3-pass
#pragma unroll
        for (int tt = 0; tt < 2; tt++) {
            uint32_t aH[4], aL[4];
            pack2(s[2 * tt][0], s[2 * tt][1], aH[0], aL[0]);
            pack2(s[2 * tt][2], s[2 * tt][3], aH[1], aL[1]);
            pack2(s[2 * tt + 1][0], s[2 * tt + 1][1], aH[2], aL[2]);
            pack2(s[2 * tt + 1][2], s[2 * tt + 1][3], aH[3], aL[3]);
            int j0 = kcol0 + tt * 16;
#pragma unroll
            for (int nd = 0; nd < 4; nd++) {
                int d0 = nd * 16;
                uint32_t bh[4], bl[4];
                {
                    int g = lane >> 3, rr = lane & 7;
                    uint32_t boff = (uint32_t)(((j0 + (g & 1) * 8 + rr) * 72 + d0 + (g >> 1) * 8) * 2);
                    ldmat_x4_t(bh, sbase + (uint32_t)((kvw + 4096) * 4) + boff);
                    ldmat_x4_t(bl, sbase + (uint32_t)((kvw + 6400) * 4) + boff);
                }
                mma_bf16(o[2 * nd], aH, bh);     mma_bf16(o[2 * nd + 1], aH, bh + 2);
                mma_bf16(o[2 * nd], aH, bl);     mma_bf16(o[2 * nd + 1], aH, bl + 2);
                mma_bf16(o[2 * nd], aL, bh);     mma_bf16(o[2 * nd + 1], aL, bh + 2);
            }
        }
        __syncthreads();
    }

    // merge the two k-slices (scratch in KV buffer 0, compute finished)
    float* smf = (float*)su;
    const int SMM = AKV0;           // m/l scratch
    const int SMO = AKV0 + 4096;    // o scratch (66-pitch rows)
    int r = mrow0 + (lane >> 2);
    if (kh2 == 1) {
        if ((lane & 3) == 0) {
            smf[SMM + r] = m0;       smf[SMM + 64 + r] = l0;
            smf[SMM + r + 8] = m8;   smf[SMM + 64 + r + 8] = l8;
        }
#pragma unroll
        for (int nd = 0; nd < 8; nd++) {
            int col = nd * 8 + (lane & 3) * 2;
            *(float2*)(smf + SMO + r * 66 + col) = make_float2(o[nd][0], o[nd][1]);
            *(float2*)(smf + SMO + (r + 8) * 66 + col) = make_float2(o[nd][2], o[nd][3]);
        }
    }
    __syncthreads();
    if (kh2 == 0) {
        float m1r = smf[SMM + r],     l1r = smf[SMM + 64 + r];
        float m1r8 = smf[SMM + r + 8], l1r8 = smf[SMM + 64 + r + 8];
        float M0 = fmaxf(m0, m1r), w00 = __expf(m0 - M0), w01 = __expf(m1r - M0);
        float L0 = l0 * w00 + l1r * w01;
        float M8 = fmaxf(m8, m1r8), w80 = __expf(m8 - M8), w81 = __expf(m1r8 - M8);
        float L8 = l8 * w80 + l1r8 * w81;
        if (!edge) {
            float i0 = 1.f / L0, i8 = 1.f / L8;
            size_t orow0 = (size_t)(b * NTOK + m * BS + r) * KH_DD + (h * DHEAD) / 2;
            size_t orow8 = (size_t)(b * NTOK + m * BS + r + 8) * KH_DD + (h * DHEAD) / 2;
#pragma unroll
            for (int nd = 0; nd < 8; nd++) {
                int col = nd * 8 + (lane & 3) * 2;
                float2 Oa = *(float2*)(smf + SMO + r * 66 + col);
                float2 Ob = *(float2*)(smf + SMO + (r + 8) * 66 + col);
                float f0 = (o[nd][0] * w00 + Oa.x * w01) * i0;
                float f1 = (o[nd][1] * w00 + Oa.y * w01) * i0;
                float f2 = (o[nd][2] * w80 + Ob.x * w81) * i8;
                float f3 = (o[nd][3] * w80 + Ob.y * w81) * i8;
                pack2(f0, f1, pch[orow0 + col / 2], pcl[orow0 + col / 2]);
                pack2(f2, f3, pch[orow8 + col / 2], pcl[orow8 + col / 2]);
            }
        } else {
            size_t pbase = ((((size_t)e * NH + h) * BB + b) * 8 + s0);
#pragma unroll
            for (int nd = 0; nd < 8; nd++) {
                int col = nd * 8 + (lane & 3) * 2;
                float2 Oa = *(float2*)(smf + SMO + r * 66 + col);
                float2 Ob = *(float2*)(smf + SMO + (r + 8) * 66 + col);
                float f0 = o[nd][0] * w00 + Oa.x * w01;
                float f1 = o[nd][1] * w00 + Oa.y * w01;
                float f2 = o[nd][2] * w80 + Ob.x * w81;
                float f3 = o[nd][3] * w80 + Ob.y * w81;
                *(float2*)(eo + pbase * 4096 + r * 64 + col) = make_float2(f0, f1);
                *(float2*)(eo + pbase * 4096 + (r + 8) * 64 + col) = make_float2(f2, f3);
            }
            if ((lane & 3) == 0) {
                em[pbase * 64 + r] = M0;     el[pbase * 64 + r] = L0;
                em[pbase * 64 + r + 8] = M8; el[pbase * 64 + r + 8] = L8;
            }
        }
    }
}

__global__ __launch_bounds__(256) void attn_edge_combine_kernel(
    const float* __restrict__ eo, const float* __restrict__ em,
    const float* __restrict__ el,
    uint32_t* __restrict__ pch, uint32_t* __restrict__ pcl)
{
    int e = blockIdx.x, h = blockIdx.y, b = blockIdx.z;
    int m = e ? (NBLK - 1) : 0;
    int t = threadIdx.x;
    int row = t >> 2, c0 = (t & 3) << 4;
    size_t base0 = ((((size_t)e * NH + h) * BB + b) * 8);

    float M = -3e38f;
#pragma unroll
    for (int s = 0; s < 8; s++) M = fmaxf(M, em[(base0 + s) * 64 + row]);
    float L = 0.f;
    float w[8];
#pragma unroll
    for (int s = 0; s < 8; s++) {
        w[s] = __expf(em[(base0 + s) * 64 + row] - M);
        L += w[s] * el[(base0 + s) * 64 + row];
    }
    float acc[16];
#pragma unroll
    for (int j = 0; j < 16; j++) acc[j] = 0.f;
#pragma unroll
    for (int s = 0; s < 8; s++) {
        const float* op = eo + (base0 + s) * 4096 + row * 64 + c0;
#pragma unroll
        for (int j = 0; j < 16; j++) acc[j] += w[s] * op[j];
    }
    float inv = 1.f / L;
    size_t orow = (size_t)(b * NTOK + m * BS + row) * KH_DD + ((h * DHEAD + c0) >> 1);
#pragma unroll
    for (int j = 0; j < 8; j++)
        pack2(acc[2 * j] * inv, acc[2 * j + 1] * inv, pch[orow + j], pcl[orow + j]);
}

// ---------------- final pooled head ----------------
__global__ __launch_bounds__(256) void final_part_kernel(
    const float* __restrict__ x, const float* __restrict__ fcw,
    float* __restrict__ part)
{
    int c = blockIdx.x, b = blockIdx.y;
    float acc = 0.f;
#pragma unroll
    for (int i = 0; i < 3; i++) {
        int d = threadIdx.x + i * 256;
        float s = 0.f;
        int n0 = c * 128;
        for (int n = n0; n < n0 + 128; n++)
            s += x[((size_t)b * NTOK + n) * DM + d];
        acc += s * fcw[d];
    }
    float dummy = 0.f;
    block_reduce2(acc, dummy);
    if (threadIdx.x == 0) part[b * 32 + c] = acc;
}

__global__ void final_sum_kernel(const float* __restrict__ part,
                                 const float* __restrict__ fcb,
                                 float* __restrict__ out)
{
    int t = threadIdx.x;
    int b = t >> 5, lane = t & 31;
    float v = part[b * 32 + lane];
#pragma unroll
    for (int off = 16; off > 0; off >>= 1)
        v += __shfl_down_sync(0xffffffffu, v, off);
    if (lane == 0) out[b] = v * (1.f / NTOK) + fcb[0];
}

// ---------------- driver ----------------
extern "C" void kernel_launch(void* const* d_in, const int* in_sizes, int n_in,
                              void* d_out, int out_size)
{
    const float* inputs = (const float*)d_in[0];
    const int*   rb_all = (const int*)d_in[1];
    const float* pos = (const float*)d_in[2];
    const float* tt  = (const float*)d_in[3];
    const float* eg  = (const float*)d_in[4];
    const float* eb  = (const float*)d_in[5];
    const float* Wq  = (const float*)d_in[6];  const float* bq = (const float*)d_in[7];
    const float* Wk  = (const float*)d_in[8];  const float* bk = (const float*)d_in[9];
    const float* Wv  = (const float*)d_in[10]; const float* bv = (const float*)d_in[11];
    const float* Wo  = (const float*)d_in[12]; const float* bo = (const float*)d_in[13];
    const float* l1g = (const float*)d_in[14]; const float* l1b = (const float*)d_in[15];
    const float* Wi  = (const float*)d_in[16]; const float* bi = (const float*)d_in[17];
    const float* Wd  = (const float*)d_in[18]; const float* bd = (const float*)d_in[19];
    const float* l2g = (const float*)d_in[20]; const float* l2b = (const float*)d_in[21];
    const float* fcw = (const float*)d_in[22]; const float* fcb = (const float*)d_in[23];
    float* out = (float*)d_out;

    float *x, *tb, *tb2, *a, *part, *eo, *em, *el, *bqkv, *zb;
    uint32_t *pqh, *pql, *pxh, *pxl, *pch, *pcl, *phh, *phl, *wh, *wl;
    cudaGetSymbolAddress((void**)&x,    g_x);
    cudaGetSymbolAddress((void**)&tb,   g_t);
    cudaGetSymbolAddress((void**)&tb2,  g_t2);
    cudaGetSymbolAddress((void**)&a,    g_a);
    cudaGetSymbolAddress((void**)&part, g_part);
    cudaGetSymbolAddress((void**)&eo,   g_eo);
    cudaGetSymbolAddress((void**)&em,   g_em);
    cudaGetSymbolAddress((void**)&el,   g_el);
    cudaGetSymbolAddress((void**)&bqkv, g_bqkv);
    cudaGetSymbolAddress((void**)&zb,   g_zb);
    cudaGetSymbolAddress((void**)&pqh,  g_pqh);
    cudaGetSymbolAddress((void**)&pql,  g_pql);
    cudaGetSymbolAddress((void**)&pxh,  g_pxh);
    cudaGetSymbolAddress((void**)&pxl,  g_pxl);
    cudaGetSymbolAddress((void**)&pch,  g_pch);
    cudaGetSymbolAddress((void**)&pcl,  g_pcl);
    cudaGetSymbolAddress((void**)&phh,  g_phh);
    cudaGetSymbolAddress((void**)&phl,  g_phl);
    cudaGetSymbolAddress((void**)&wh,   g_wh);
    cudaGetSymbolAddress((void**)&wl,   g_wl);

    const int ATTN_SMEM = (AKV0 + 2 * KVSZ) * 4;  // 86016 bytes
    const int GEMM_SMEM = 2 * 32768;              // 65536 bytes
    cudaFuncSetAttribute((const void*)attn_mma_kernel, cudaFuncAttributeMaxDynamicSharedMemorySize, ATTN_SMEM);
    cudaFuncSetAttribute((const void*)mgemm_kernel<0, 0>, cudaFuncAttributeMaxDynamicSharedMemorySize, GEMM_SMEM);
    cudaFuncSetAttribute((const void*)mgemm_kernel<0, 1>, cudaFuncAttributeMaxDynamicSharedMemorySize, GEMM_SMEM);
    cudaFuncSetAttribute((const void*)mgemm_kernel<1, 1>, cudaFuncAttributeMaxDynamicSharedMemorySize, GEMM_SMEM);

    const int MROWS = BB * NTOK;                 // 8192
    dim3 gemm_qkv(GS / 128, MROWS / 128, 1);     // (18, 64)
    dim3 gemm_dd2(DM / 128, MROWS / 128, 2);     // (6, 64, 2) split-K
    dim3 gemm_ff(FFD / 128, MROWS / 128, 1);     // (24, 64)

    embed_ln_kernel<<<MROWS / 8, 256>>>(inputs, pos, tt, eg, eb, x, pxh, pxl);
    pack_wA_kernel<<<dim3(DM / 32, DM / 64, 8), 256>>>(Wq, Wk, Wv, Wo, wh, wl);
    pack_wB_kernel<<<dim3(FFD / 32, DM / 64, 2), 256>>>(Wi, wh, wl);
    pack_wC_kernel<<<dim3(DM / 32, FFD / 64, 2), 256>>>(Wd, wh, wl);
    concat_bias_kernel<<<18, 256>>>(bq, bk, bv, bqkv);

    for (int l = 0; l < NL; l++) {
        const uint32_t* whl = wh + (size_t)l * LOFF;
        const uint32_t* wll = wl + (size_t)l * LOFF;

        // fused QKV GEMM -> packed output
        mgemm_kernel<0, 1><<<gemm_qkv, 256, GEMM_SMEM>>>(
            pxh, pxl, whl, wll, bqkv + l * GS, nullptr, pqh, pql,
            nullptr, nullptr, KH_DD, KH_DD / 16, GS);

        // unified attention (middles + edge partials in one launch)
        attn_mma_kernel<<<dim3(NBLK - 2 + 16, NH, BB), 256, ATTN_SMEM>>>(
            pqh, pql, rb_all + l * NH * NBLK * RR, pch, pcl, eo, em, el);
        attn_edge_combine_kernel<<<dim3(2, NH, BB), 256>>>(eo, em, el, pch, pcl);

        // Wo GEMM split-K=2
        mgemm_kernel<0, 0><<<gemm_dd2, 256, GEMM_SMEM>>>(
            pch, pcl, whl + WO_OFF, wll + WO_OFF, bo + l * DM, tb, nullptr, nullptr,
            zb, tb2, KH_DD, KH_DD / 32, DM);
        ln_add3_kernel<<<MROWS / 8, 256>>>(x, tb, tb2, l1g + l * DM, l1b + l * DM, a, pxh, pxl);

        mgemm_kernel<1, 1><<<gemm_ff, 256, GEMM_SMEM>>>(
            pxh, pxl, whl + WI_OFF, wll + WI_OFF, bi + l * FFD, nullptr, phh, phl,
            nullptr, nullptr, KH_DD, KH_DD / 16, FFD);

        // Wd GEMM split-K=2
        mgemm_kernel<0, 0><<<gemm_dd2, 256, GEMM_SMEM>>>(
            phh, phl, whl + WD_OFF, wll + WD_OFF, bd + l * DM, tb, nullptr, nullptr,
            zb, tb2, KH_FF, KH_FF / 32, DM);
        ln_add3_kernel<<<MROWS / 8, 256>>>(a, tb, tb2, l2g + l * DM, l2b + l * DM, x, pxh, pxl);
    }

    final_part_kernel<<<dim3(32, BB), 256>>>(x, fcw, part);
    final_sum_kernel<<<1, 64>>>(part, fcb, out);
}

// round 16
// speedup vs baseline: 1.5283x; 1.5283x over previous
#include <cuda_runtime.h>
#include <math.h>
#include <stdint.h>

#define BB 2
#define NTOK 4096
#define DM 768
#define NH 12
#define DHEAD 64
#define NBLK 64
#define BS 64
#define FFD 3072
#define NL 2
#define RR 3
#define KH_DD (DM / 2)    // 384
#define KH_FF (FFD / 2)   // 1536
#define GS 2304           // fused qkv width
#define PQS (GS / 2)      // 1152 packed row stride

// packed weight layout per layer (uint32 words)
#define QKV_WORDS (GS * KH_DD)
#define WO_OFF    QKV_WORDS
#define WI_OFF    (WO_OFF + DM * KH_DD)
#define WD_OFF    (WI_OFF + FFD * KH_DD)
#define LOFF      (WD_OFF + DM * KH_FF)

// ---------------- scratch ----------------
__device__ float g_x[BB * NTOK * DM];
__device__ float g_t[BB * NTOK * DM];
__device__ float g_t2[BB * NTOK * DM];
__device__ float g_a[BB * NTOK * DM];
__device__ float g_part[BB * 32];
__device__ float g_bqkv[2 * GS];
__device__ float g_zb[DM];                      // zero bias (.bss)
__device__ uint32_t g_pqh[BB * NTOK * PQS];
__device__ uint32_t g_pql[BB * NTOK * PQS];
__device__ uint32_t g_pxh[BB * NTOK * KH_DD];
__device__ uint32_t g_pxl[BB * NTOK * KH_DD];
__device__ uint32_t g_pch[BB * NTOK * KH_DD];
__device__ uint32_t g_pcl[BB * NTOK * KH_DD];
__device__ uint32_t g_phh[BB * NTOK * KH_FF];
__device__ uint32_t g_phl[BB * NTOK * KH_FF];
__device__ uint32_t g_wh[2 * LOFF];
__device__ uint32_t g_wl[2 * LOFF];
__device__ float g_eo[2 * NH * BB * 8 * 64 * 64];
__device__ float g_em[2 * NH * BB * 8 * 64];
__device__ float g_el[2 * NH * BB * 8 * 64];

// ---------------- helpers ----------------
__device__ __forceinline__ uint32_t f2bf(float x) {
    uint32_t u = __float_as_uint(x);
    return (u + 0x7FFFu + ((u >> 16) & 1u)) >> 16;
}
__device__ __forceinline__ float bf2f(uint32_t h) { return __uint_as_float(h << 16); }
__device__ __forceinline__ void pack2(float a, float b, uint32_t& hi, uint32_t& lo) {
    uint32_t h0 = f2bf(a), h1 = f2bf(b);
    hi = h0 | (h1 << 16);
    lo = f2bf(a - bf2f(h0)) | (f2bf(b - bf2f(h1)) << 16);
}
__device__ __forceinline__ uint32_t smem_u32(const void* p) {
    uint32_t a;
    asm("{ .reg .u64 t; cvta.to.shared.u64 t, %1; cvt.u32.u64 %0, t; }" : "=r"(a) : "l"(p));
    return a;
}
__device__ __forceinline__ void cp16(uint32_t saddr, const void* g) {
    asm volatile("cp.async.ca.shared.global [%0], [%1], 16;" :: "r"(saddr), "l"(g));
}
#define CP_COMMIT() asm volatile("cp.async.commit_group;" ::: "memory")
#define CP_WAIT1()  asm volatile("cp.async.wait_group 1;" ::: "memory")
#define CP_WAIT0()  asm volatile("cp.async.wait_group 0;" ::: "memory")

__device__ __forceinline__ void ldmat_x4(uint32_t* r, uint32_t saddr) {
    asm volatile("ldmatrix.sync.aligned.m8n8.x4.shared.b16 {%0,%1,%2,%3}, [%4];"
                 : "=r"(r[0]), "=r"(r[1]), "=r"(r[2]), "=r"(r[3]) : "r"(saddr));
}
__device__ __forceinline__ void ldmat_x4_t(uint32_t* r, uint32_t saddr) {
    asm volatile("ldmatrix.sync.aligned.m8n8.x4.trans.shared.b16 {%0,%1,%2,%3}, [%4];"
                 : "=r"(r[0]), "=r"(r[1]), "=r"(r[2]), "=r"(r[3]) : "r"(saddr));
}
__device__ __forceinline__ void mma_bf16(float* c, const uint32_t* a, const uint32_t* b) {
    asm volatile(
        "mma.sync.aligned.m16n8k16.row.col.f32.bf16.bf16.f32 "
        "{%0,%1,%2,%3}, {%4,%5,%6,%7}, {%8,%9}, {%0,%1,%2,%3};"
        : "+f"(c[0]), "+f"(c[1]), "+f"(c[2]), "+f"(c[3])
        : "r"(a[0]), "r"(a[1]), "r"(a[2]), "r"(a[3]), "r"(b[0]), "r"(b[1]));
}

// ---------------- batched weight packs ----------------
__device__ __forceinline__ void pack_tile(
    const float* __restrict__ W, uint32_t* __restrict__ hi, uint32_t* __restrict__ lo,
    int K, int N, int Kh, int k0, int n0, size_t dbase)
{
    __shared__ float tile[64][33];
    int t = threadIdx.x;
    for (int i = t; i < 64 * 32; i += 256) {
        int r = i >> 5, c = i & 31;
        tile[r][c] = W[(size_t)(k0 + r) * N + n0 + c];
    }
    __syncthreads();
    for (int i = t; i < 32 * 32; i += 256) {
        int n = i >> 5, kp = i & 31;
        size_t o = dbase + (size_t)(n0 + n) * Kh + (k0 >> 1) + kp;
        pack2(tile[kp * 2][n], tile[kp * 2 + 1][n], hi[o], lo[o]);
    }
}

__global__ __launch_bounds__(256) void pack_wA_kernel(
    const float* __restrict__ Wq, const float* __restrict__ Wk,
    const float* __restrict__ Wv, const float* __restrict__ Wo,
    uint32_t* __restrict__ hi, uint32_t* __restrict__ lo)
{
    int z = blockIdx.z, layer = z >> 2, which = z & 3;
    const float* W = (which == 0 ? Wq : which == 1 ? Wk : which == 2 ? Wv : Wo)
                     + (size_t)layer * DM * DM;
    size_t dbase = (size_t)layer * LOFF +
                   (which < 3 ? (size_t)which * DM * KH_DD : (size_t)WO_OFF);
    pack_tile(W, hi, lo, DM, DM, KH_DD, blockIdx.y * 64, blockIdx.x * 32, dbase);
}

__global__ __launch_bounds__(256) void pack_wB_kernel(
    const float* __restrict__ Wi, uint32_t* __restrict__ hi, uint32_t* __restrict__ lo)
{
    int layer = blockIdx.z;
    pack_tile(Wi + (size_t)layer * DM * FFD, hi, lo, DM, FFD, KH_DD,
              blockIdx.y * 64, blockIdx.x * 32, (size_t)layer * LOFF + WI_OFF);
}

__global__ __launch_bounds__(256) void pack_wC_kernel(
    const float* __restrict__ Wd, uint32_t* __restrict__ hi, uint32_t* __restrict__ lo)
{
    int layer = blockIdx.z;
    pack_tile(Wd + (size_t)layer * FFD * DM, hi, lo, FFD, DM, KH_FF,
              blockIdx.y * 64, blockIdx.x * 32, (size_t)layer * LOFF + WD_OFF);
}

__global__ void concat_bias_kernel(const float* __restrict__ a, const float* __restrict__ b,
                                   const float* __restrict__ c, float* __restrict__ o)
{
    int t = blockIdx.x * 256 + threadIdx.x;
    if (t >= 2 * GS) return;
    int l = t / GS, j = t - l * GS;
    float v;
    if (j < DM) v = a[l * DM + j];
    else if (j < 2 * DM) v = b[l * DM + j - DM];
    else v = c[l * DM + j - 2 * DM];
    o[t] = v;
}

// ---------------- block reduce (final head only) ----------------
__device__ __forceinline__ void block_reduce2(float& s, float& s2) {
#pragma unroll
    for (int off = 16; off > 0; off >>= 1) {
        s  += __shfl_down_sync(0xffffffffu, s, off);
        s2 += __shfl_down_sync(0xffffffffu, s2, off);
    }
    __shared__ float sh[16];
    int w = threadIdx.x >> 5, lane = threadIdx.x & 31;
    if (lane == 0) { sh[w] = s; sh[8 + w] = s2; }
    __syncthreads();
    if (threadIdx.x == 0) {
        float a = 0.f, b = 0.f;
#pragma unroll
        for (int i = 0; i < 8; i++) { a += sh[i]; b += sh[8 + i]; }
        sh[0] = a; sh[8] = b;
    }
    __syncthreads();
    s = sh[0]; s2 = sh[8];
}

// ---------------- warp-per-row LN kernels ----------------
__device__ __forceinline__ void ln_warp_finish(
    float2* v, int lane, const float* g, const float* bta,
    float* out, uint32_t* ph, uint32_t* pl, size_t rowp)
{
    float s = 0.f, s2 = 0.f;
#pragma unroll
    for (int j = 0; j < 12; j++) {
        s  += v[j].x + v[j].y;
        s2 += v[j].x * v[j].x + v[j].y * v[j].y;
    }
#pragma unroll
    for (int off = 16; off > 0; off >>= 1) {
        s  += __shfl_xor_sync(0xffffffffu, s, off);
        s2 += __shfl_xor_sync(0xffffffffu, s2, off);
    }
    float mean = s * (1.f / DM);
    float var = s2 * (1.f / DM) - mean * mean;
    float rstd = rsqrtf(var + 1e-12f);
#pragma unroll
    for (int j = 0; j < 12; j++) {
        int idx = lane + j * 32;
        float2 gg = ((const float2*)g)[idx];
        float2 bb = ((const float2*)bta)[idx];
        float a = (v[j].x - mean) * rstd * gg.x + bb.x;
        float b = (v[j].y - mean) * rstd * gg.y + bb.y;
        ((float2*)out)[rowp + idx] = make_float2(a, b);
        pack2(a, b, ph[rowp + idx], pl[rowp + idx]);
    }
}

__global__ __launch_bounds__(256) void embed_ln_kernel(
    const float* __restrict__ e, const float* __restrict__ pos,
    const float* __restrict__ tt, const float* __restrict__ g,
    const float* __restrict__ bta, float* __restrict__ out,
    uint32_t* __restrict__ ph, uint32_t* __restrict__ pl)
{
    int warp = threadIdx.x >> 5, lane = threadIdx.x & 31;
    int row = blockIdx.x * 8 + warp;
    size_t rowp = (size_t)row * 384;
    size_t posp = (size_t)(row & (NTOK - 1)) * 384;
    float2 v[12];
#pragma unroll
    for (int j = 0; j < 12; j++) {
        int idx = lane + j * 32;
        float2 a = ((const float2*)e)[rowp + idx];
        float2 p = ((const float2*)pos)[posp + idx];
        float2 q = ((const float2*)tt)[idx];
        v[j] = make_float2(a.x + p.x + q.x, a.y + p.y + q.y);
    }
    ln_warp_finish(v, lane, g, bta, out, ph, pl, rowp);
}

// out = LN(r + y1 + y2)
__global__ __launch_bounds__(256) void ln_add3_kernel(
    const float* __restrict__ r, const float* __restrict__ y1,
    const float* __restrict__ y2,
    const float* __restrict__ g, const float* __restrict__ bta,
    float* __restrict__ out, uint32_t* __restrict__ ph, uint32_t* __restrict__ pl)
{
    int warp = threadIdx.x >> 5, lane = threadIdx.x & 31;
    int row = blockIdx.x * 8 + warp;
    size_t rowp = (size_t)row * 384;
    float2 v[12];
#pragma unroll
    for (int j = 0; j < 12; j++) {
        int idx = lane + j * 32;
        float2 a = ((const float2*)r)[rowp + idx];
        float2 b = ((const float2*)y1)[rowp + idx];
        float2 c = ((const float2*)y2)[rowp + idx];
        v[j] = make_float2(a.x + b.x + c.x, a.y + b.y + c.y);
    }
    ln_warp_finish(v, lane, g, bta, out, ph, pl, rowp);
}

// ---------------- packed bf16 3-pass GEMM (2-stage pipeline + optional split-K) ----------------
template<int GELU, int PACK>
__global__ __launch_bounds__(256, 2) void mgemm_kernel(
    const uint32_t* __restrict__ Ah, const uint32_t* __restrict__ Al,
    const uint32_t* __restrict__ Bh, const uint32_t* __restrict__ Bl,
    const float* __restrict__ bias, float* __restrict__ C,
    uint32_t* __restrict__ Oh, uint32_t* __restrict__ Ol,
    const float* __restrict__ bias2, float* __restrict__ C2,
    int Kh, int kcnt, int Nn)
{
    extern __shared__ uint32_t sm[];
    uint32_t smem_addr = smem_u32(sm);
    const int RAH = 0, RAL = 2048, RBH = 4096, RBL = 6144;
    const uint32_t BUF_BYTES = 32768;

    const int t = threadIdx.x;
    const int wid = t >> 5, lane = t & 31;
    const int wr0 = (wid >> 1) * 32;
    const int wc0 = (wid & 1) * 64;
    const int lr = lane >> 2, lc = lane & 3;
    const int aRow0 = blockIdx.y * 128;
    const int bRow0 = blockIdx.x * 128;
    int kpBase = 0;
    if (blockIdx.z) { kpBase = kcnt * 16; bias = bias2; C = C2; }

    float acc[2][8][4];
#pragma unroll
    for (int i = 0; i < 2; i++)
#pragma unroll
        for (int j = 0; j < 8; j++)
#pragma unroll
            for (int q = 0; q < 4; q++) acc[i][j][q] = 0.f;

    auto ISSUE = [&](int c) {
        uint32_t sb = smem_addr + (uint32_t)(c & 1) * BUF_BYTES;
        int kp0 = kpBase + c * 16;
#pragma unroll
        for (int i = 0; i < 8; i++) {
            int reg = i >> 1;
            int f = t + (i & 1) * 256;
            int row = f >> 2, w4 = f & 3;
            int sw = (w4 ^ ((row >> 1) & 3)) << 2;
            const uint32_t* g;
            int ro;
            if (reg == 0)      { g = Ah + (size_t)(aRow0 + row) * Kh + kp0 + w4 * 4; ro = RAH; }
            else if (reg == 1) { g = Al + (size_t)(aRow0 + row) * Kh + kp0 + w4 * 4; ro = RAL; }
            else if (reg == 2) { g = Bh + (size_t)(bRow0 + row) * Kh + kp0 + w4 * 4; ro = RBH; }
            else               { g = Bl + (size_t)(bRow0 + row) * Kh + kp0 + w4 * 4; ro = RBL; }
            cp16(sb + (uint32_t)(ro + row * 16 + sw) * 4u, g);
        }
        CP_COMMIT();
    };

    uint32_t ah_[2][4], al_[2][4], bf[8][2];
    auto LDA = [&](uint32_t (&dst)[2][4], uint32_t sb, int regOff, int s) {
#pragma unroll
        for (int mt = 0; mt < 2; mt++) {
            int row = wr0 + mt * 16 + (lane & 15);
            int c4 = (2 * s + (lane >> 4)) ^ ((row >> 1) & 3);
            ldmat_x4(dst[mt], sb + (uint32_t)((regOff + row * 16 + (c4 << 2)) * 4));
        }
    };
    auto LDB = [&](uint32_t sb, int regOff, int s) {
#pragma unroll
        for (int nt0 = 0; nt0 < 8; nt0 += 2) {
            int row = wc0 + nt0 * 8 + ((lane & 16) >> 1) + (lane & 7);
            int c4 = (2 * s + ((lane & 8) >> 3)) ^ ((row >> 1) & 3);
            uint32_t regs[4];
            ldmat_x4(regs, sb + (uint32_t)((regOff + row * 16 + (c4 << 2)) * 4));
            bf[nt0][0] = regs[0]; bf[nt0][1] = regs[1];
            bf[nt0 + 1][0] = regs[2]; bf[nt0 + 1][1] = regs[3];
        }
    };
    auto MMAS = [&](uint32_t (&a)[2][4]) {
#pragma unroll
        for (int mt = 0; mt < 2; mt++)
#pragma unroll
            for (int nt = 0; nt < 8; nt++) mma_bf16(acc[mt][nt], a[mt], bf[nt]);
    };
    auto COMP = [&](int buf) {
        uint32_t sb = smem_addr + (uint32_t)buf * BUF_BYTES;
#pragma unroll
        for (int s = 0; s < 2; s++) {
            LDA(ah_, sb, RAH, s);
            LDA(al_, sb, RAL, s);
            LDB(sb, RBH, s);
            MMAS(ah_);            // hh
            MMAS(al_);            // lh
            LDB(sb, RBL, s);
            MMAS(ah_);            // hl
        }
    };

    const int nch = kcnt;
    ISSUE(0);
    if (nch > 1) ISSUE(1);
    for (int c = 0; c < nch; c++) {
        if (c + 1 < nch) { CP_WAIT1(); } else { CP_WAIT0(); }
        __syncthreads();
        COMP(c & 1);
        __syncthreads();
        if (c + 2 < nch) ISSUE(c + 2);
    }

    const int Khn = Nn >> 1;
#pragma unroll
    for (int mt = 0; mt < 2; mt++) {
        int r = blockIdx.y * 128 + wr0 + mt * 16 + lr;
#pragma unroll
        for (int nt = 0; nt < 8; nt++) {
            int cc = blockIdx.x * 128 + wc0 + nt * 8 + lc * 2;
            float2 bb = *(const float2*)(bias + cc);
            float v[4];
            v[0] = acc[mt][nt][0] + bb.x; v[1] = acc[mt][nt][1] + bb.y;
            v[2] = acc[mt][nt][2] + bb.x; v[3] = acc[mt][nt][3] + bb.y;
            if (GELU) {
#pragma unroll
                for (int q = 0; q < 4; q++) {
                    float z = 0.7978845608028654f * (v[q] + 0.044715f * v[q] * v[q] * v[q]);
                    float e = __expf(2.f * z);
                    v[q] = 0.5f * v[q] * (2.f - 2.f / (e + 1.f));
                }
            }
            if (PACK) {
                int kp = cc >> 1;
                pack2(v[0], v[1], Oh[(size_t)r * Khn + kp], Ol[(size_t)r * Khn + kp]);
                pack2(v[2], v[3], Oh[(size_t)(r + 8) * Khn + kp], Ol[(size_t)(r + 8) * Khn + kp]);
            } else {
                *(float2*)(C + (size_t)r * Nn + cc) = make_float2(v[0], v[1]);
                *(float2*)(C + (size_t)(r + 8) * Nn + cc) = make_float2(v[2], v[3]);
            }
        }
    }
}

// ---------------- attention: unified mma flash kernel on packed qkv ----------------
// grid.x: [0, 62) middle q-blocks (m = x+1); [62, 78) edge partials
// (idx = x-62: e = idx>>3, s0 = idx&7).
__global__ __launch_bounds__(256) void attn_mma_kernel(
    const uint32_t* __restrict__ pqh, const uint32_t* __restrict__ pql,
    const int* __restrict__ rb,
    uint32_t* __restrict__ pch, uint32_t* __restrict__ pcl,
    float* __restrict__ eo, float* __restrict__ em, float* __restrict__ el)
{
    extern __shared__ uint32_t su[];
    uint32_t sbase = smem_u32(su);
    const int RQH = 0, RQL = 2048, RKH = 4096, RKL = 6144, RVH = 8192, RVL = 10496;
    int t = threadIdx.x, wid = t >> 5, lane = t & 31;
    int mrow0 = (wid & 3) * 16;
    int kh2 = wid >> 2;
    int kcol0 = kh2 * 32;

    int h = blockIdx.y, b = blockIdx.z;
    int x = blockIdx.x;
    bool edge = (x >= NBLK - 2);
    int m, s0 = 0, e = 0;
    if (edge) {
        int idx = x - (NBLK - 2);
        e = idx >> 3; s0 = idx & 7;
        m = e ? (NBLK - 1) : 0;
    } else m = x + 1;

    const uint32_t* qh = pqh + (size_t)(b * NTOK + m * BS) * PQS + h * 32;
    const uint32_t* ql = pql + (size_t)(b * NTOK + m * BS) * PQS + h * 32;
    const uint32_t* kbh = pqh + (size_t)b * NTOK * PQS + KH_DD + h * 32;
    const uint32_t* kbl = pql + (size_t)b * NTOK * PQS + KH_DD + h * 32;
    const uint32_t* vbh = pqh + (size_t)b * NTOK * PQS + 2 * KH_DD + h * 32;
    const uint32_t* vbl = pql + (size_t)b * NTOK * PQS + 2 * KH_DD + h * 32;

    for (int u = t; u < 512; u += 256) {
        int r = u >> 3, c4 = u & 7;
        uint32_t doff = (uint32_t)((r * 32 + ((c4 ^ (r & 7)) << 2)) * 4);
        cp16(sbase + (uint32_t)(RQH * 4) + doff, qh + (size_t)r * PQS + c4 * 4);
        cp16(sbase + (uint32_t)(RQL * 4) + doff, ql + (size_t)r * PQS + c4 * 4);
    }
    CP_COMMIT();

    int list[8];
    if (!edge) {
        const int* r3 = rb + (h * NBLK + m) * RR;
        list[0] = 0; list[1] = NBLK - 1;
        list[2] = m - 1; list[3] = m; list[4] = m + 1;
        list[5] = r3[0]; list[6] = r3[1]; list[7] = r3[2];
    }

    float o[8][4];
#pragma unroll
    for (int i = 0; i < 8; i++)
#pragma unroll
        for (int j = 0; j < 4; j++) o[i][j] = 0.f;
    float m0 = -1e30f, m8 = -1e30f, l0 = 0.f, l8 = 0.f;

    for (int step = 0; step < 8; step++) {
        int blk = edge ? (s0 * 8 + step) : list[step];
        const uint32_t* kh = kbh + (size_t)(blk * BS) * PQS;
        const uint32_t* kl = kbl + (size_t)(blk * BS) * PQS;
        const uint32_t* vh = vbh + (size_t)(blk * BS) * PQS;
        const uint32_t* vl = vbl + (size_t)(blk * BS) * PQS;
        for (int u = t; u < 512; u += 256) {
            int r = u >> 3, c4 = u & 7;
            uint32_t doff = (uint32_t)((r * 32 + ((c4 ^ (r & 7)) << 2)) * 4);
            cp16(sbase + (uint32_t)(RKH * 4) + doff, kh + (size_t)r * PQS + c4 * 4);
            cp16(sbase + (uint32_t)(RKL * 4) + doff, kl + (size_t)r * PQS + c4 * 4);
        }
        for (int u = t; u < 512; u += 256) {
            int j = u >> 3, w4 = u & 7;
            uint32_t doff = (uint32_t)((j * 36 + w4 * 4) * 4);
            cp16(sbase + (uint32_t)(RVH * 4) + doff, vh + (size_t)j * PQS + w4 * 4);
            cp16(sbase + (uint32_t)(RVL * 4) + doff, vl + (size_t)j * PQS + w4 * 4);
        }
        CP_COMMIT();
        CP_WAIT0();
        __syncthreads();

        // QK^T 3-pass
        float s[4][4];
#pragma unroll
        for (int i = 0; i < 4; i++)
#pragma unroll
            for (int j = 0; j < 4; j++) s[i][j] = 0.f;
#pragma unroll
        for (int ks = 0; ks < 4; ks++) {
            uint32_t aH[4], aL[4];
            {
                int r = mrow0 + (lane & 15);
                int c4 = (2 * ks + (lane >> 4)) ^ (r & 7);
                ldmat_x4(aH, sbase + (uint32_t)((RQH + r * 32 + (c4 << 2)) * 4));
                ldmat_x4(aL, sbase + (uint32_t)((RQL + r * 32 + (c4 << 2)) * 4));
            }
#pragma unroll
            for (int ntp = 0; ntp < 4; ntp += 2) {
                uint32_t bh[4], bl[4];
                {
                    int r = kcol0 + ntp * 8 + ((lane & 16) >> 1) + (lane & 7);
                    int c4 = (2 * ks + ((lane & 8) >> 3)) ^ (r & 7);
                    ldmat_x4(bh, sbase + (uint32_t)((RKH + r * 32 + (c4 << 2)) * 4));
                    ldmat_x4(bl, sbase + (uint32_t)((RKL + r * 32 + (c4 << 2)) * 4));
                }
                mma_bf16(s[ntp], aH, bh);     mma_bf16(s[ntp + 1], aH, bh + 2);
                mma_bf16(s[ntp], aH, bl);     mma_bf16(s[ntp + 1], aH, bl + 2);
                mma_bf16(s[ntp], aL, bh);     mma_bf16(s[ntp + 1], aL, bh + 2);
            }
        }

        // softmax (slice-local online)
        float mx0 = -1e30f, mx8 = -1e30f;
#pragma unroll
        for (int nt = 0; nt < 4; nt++) {
#pragma unroll
            for (int j = 0; j < 4; j++) s[nt][j] *= 0.125f;
            mx0 = fmaxf(mx0, fmaxf(s[nt][0], s[nt][1]));
            mx8 = fmaxf(mx8, fmaxf(s[nt][2], s[nt][3]));
        }
        mx0 = fmaxf(mx0, __shfl_xor_sync(0xffffffffu, mx0, 1));
        mx0 = fmaxf(mx0, __shfl_xor_sync(0xffffffffu, mx0, 2));
        mx8 = fmaxf(mx8, __shfl_xor_sync(0xffffffffu, mx8, 1));
        mx8 = fmaxf(mx8, __shfl_xor_sync(0xffffffffu, mx8, 2));
        float mn0 = fmaxf(m0, mx0), mn8 = fmaxf(m8, mx8);
        float c0 = __expf(m0 - mn0), c8 = __expf(m8 - mn8);
        float ls0 = 0.f, ls8 = 0.f;
#pragma unroll
        for (int nt = 0; nt < 4; nt++) {
            s[nt][0] = __expf(s[nt][0] - mn0); ls0 += s[nt][0];
            s[nt][1] = __expf(s[nt][1] - mn0); ls0 += s[nt][1];
            s[nt][2] = __expf(s[nt][2] - mn8); ls8 += s[nt][2];
            s[nt][3] = __expf(s[nt][3] - mn8); ls8 += s[nt][3];
        }
        ls0 += __shfl_xor_sync(0xffffffffu, ls0, 1);
        ls0 += __shfl_xor_sync(0xffffffffu, ls0, 2);
        ls8 += __shfl_xor_sync(0xffffffffu, ls8, 1);
        ls8 += __shfl_xor_sync(0xffffffffu, ls8, 2);
        l0 = l0 * c0 + ls0; l8 = l8 * c8 + ls8;
        m0 = mn0; m8 = mn8;
#pragma unroll
        for (int nd = 0; nd < 8; nd++) {
            o[nd][0] *= c0; o[nd][1] *= c0;
            o[nd][2] *= c8; o[nd][3] *= c8;
        }

        // PV 3-pass
#pragma unroll
        for (int tt = 0; tt < 2; tt++) {
            uint32_t aH[4], aL[4];
            pack2(s[2 * tt][0], s[2 * tt][1], aH[0], aL[0]);
            pack2(s[2 * tt][2], s[2 * tt][3], aH[1], aL[1]);
            pack2(s[2 * tt + 1][0], s[2 * tt + 1][1], aH[2], aL[2]);
            pack2(s[2 * tt + 1][2], s[2 * tt + 1][3], aH[3], aL[3]);
            int j0 = kcol0 + tt * 16;
#pragma unroll
            for (int nd = 0; nd < 4; nd++) {
                int d0 = nd * 16;
                uint32_t bh[4], bl[4];
                {
                    int g = lane >> 3, rr = lane & 7;
                    uint32_t boff = (uint32_t)(((j0 + (g & 1) * 8 + rr) * 72 + d0 + (g >> 1) * 8) * 2);
                    ldmat_x4_t(bh, sbase + (uint32_t)(RVH * 4) + boff);
                    ldmat_x4_t(bl, sbase + (uint32_t)(RVL * 4) + boff);
                }
                mma_bf16(o[2 * nd], aH, bh);     mma_bf16(o[2 * nd + 1], aH, bh + 2);
                mma_bf16(o[2 * nd], aH, bl);     mma_bf16(o[2 * nd + 1], aH, bl + 2);
                mma_bf16(o[2 * nd], aL, bh);     mma_bf16(o[2 * nd + 1], aL, bh + 2);
            }
        }
        __syncthreads();
    }

    // merge the two k-slices
    float* smf = (float*)su;
    int r = mrow0 + (lane >> 2);
    if (kh2 == 1) {
        if ((lane & 3) == 0) {
            smf[RKH + r] = m0;       smf[RKH + 64 + r] = l0;
            smf[RKH + r + 8] = m8;   smf[RKH + 64 + r + 8] = l8;
        }
#pragma unroll
        for (int nd = 0; nd < 8; nd++) {
            int col = nd * 8 + (lane & 3) * 2;
            *(float2*)(smf + RVH + r * 66 + col) = make_float2(o[nd][0], o[nd][1]);
            *(float2*)(smf + RVH + (r + 8) * 66 + col) = make_float2(o[nd][2], o[nd][3]);
        }
    }
    __syncthreads();
    if (kh2 == 0) {
        float m1r = smf[RKH + r],     l1r = smf[RKH + 64 + r];
        float m1r8 = smf[RKH + r + 8], l1r8 = smf[RKH + 64 + r + 8];
        float M0 = fmaxf(m0, m1r), w00 = __expf(m0 - M0), w01 = __expf(m1r - M0);
        float L0 = l0 * w00 + l1r * w01;
        float M8 = fmaxf(m8, m1r8), w80 = __expf(m8 - M8), w81 = __expf(m1r8 - M8);
        float L8 = l8 * w80 + l1r8 * w81;
        if (!edge) {
            float i0 = 1.f / L0, i8 = 1.f / L8;
            size_t orow0 = (size_t)(b * NTOK + m * BS + r) * KH_DD + (h * DHEAD) / 2;
            size_t orow8 = (size_t)(b * NTOK + m * BS + r + 8) * KH_DD + (h * DHEAD) / 2;
#pragma unroll
            for (int nd = 0; nd < 8; nd++) {
                int col = nd * 8 + (lane & 3) * 2;
                float2 Oa = *(float2*)(smf + RVH + r * 66 + col);
                float2 Ob = *(float2*)(smf + RVH + (r + 8) * 66 + col);
                float f0 = (o[nd][0] * w00 + Oa.x * w01) * i0;
                float f1 = (o[nd][1] * w00 + Oa.y * w01) * i0;
                float f2 = (o[nd][2] * w80 + Ob.x * w81) * i8;
                float f3 = (o[nd][3] * w80 + Ob.y * w81) * i8;
                pack2(f0, f1, pch[orow0 + col / 2], pcl[orow0 + col / 2]);
                pack2(f2, f3, pch[orow8 + col / 2], pcl[orow8 + col / 2]);
            }
        } else {
            size_t pbase = ((((size_t)e * NH + h) * BB + b) * 8 + s0);
#pragma unroll
            for (int nd = 0; nd < 8; nd++) {
                int col = nd * 8 + (lane & 3) * 2;
                float2 Oa = *(float2*)(smf + RVH + r * 66 + col);
                float2 Ob = *(float2*)(smf + RVH + (r + 8) * 66 + col);
                float f0 = o[nd][0] * w00 + Oa.x * w01;
                float f1 = o[nd][1] * w00 + Oa.y * w01;
                float f2 = o[nd][2] * w80 + Ob.x * w81;
                float f3 = o[nd][3] * w80 + Ob.y * w81;
                *(float2*)(eo + pbase * 4096 + r * 64 + col) = make_float2(f0, f1);
                *(float2*)(eo + pbase * 4096 + (r + 8) * 64 + col) = make_float2(f2, f3);
            }
            if ((lane & 3) == 0) {
                em[pbase * 64 + r] = M0;     el[pbase * 64 + r] = L0;
                em[pbase * 64 + r + 8] = M8; el[pbase * 64 + r + 8] = L8;
            }
        }
    }
}

__global__ __launch_bounds__(256) void attn_edge_combine_kernel(
    const float* __restrict__ eo, const float* __restrict__ em,
    const float* __restrict__ el,
    uint32_t* __restrict__ pch, uint32_t* __restrict__ pcl)
{
    int e = blockIdx.x, h = blockIdx.y, b = blockIdx.z;
    int m = e ? (NBLK - 1) : 0;
    int t = threadIdx.x;
    int row = t >> 2, c0 = (t & 3) << 4;
    size_t base0 = ((((size_t)e * NH + h) * BB + b) * 8);

    float M = -3e38f;
#pragma unroll
    for (int s = 0; s < 8; s++) M = fmaxf(M, em[(base0 + s) * 64 + row]);
    float L = 0.f;
    float w[8];
#pragma unroll
    for (int s = 0; s < 8; s++) {
        w[s] = __expf(em[(base0 + s) * 64 + row] - M);
        L += w[s] * el[(base0 + s) * 64 + row];
    }
    float acc[16];
#pragma unroll
    for (int j = 0; j < 16; j++) acc[j] = 0.f;
#pragma unroll
    for (int s = 0; s < 8; s++) {
        const float* op = eo + (base0 + s) * 4096 + row * 64 + c0;
#pragma unroll
        for (int j = 0; j < 16; j++) acc[j] += w[s] * op[j];
    }
    float inv = 1.f / L;
    size_t orow = (size_t)(b * NTOK + m * BS + row) * KH_DD + ((h * DHEAD + c0) >> 1);
#pragma unroll
    for (int j = 0; j < 8; j++)
        pack2(acc[2 * j] * inv, acc[2 * j + 1] * inv, pch[orow + j], pcl[orow + j]);
}

// ---------------- final pooled head ----------------
__global__ __launch_bounds__(256) void final_part_kernel(
    const float* __restrict__ x, const float* __restrict__ fcw,
    float* __restrict__ part)
{
    int c = blockIdx.x, b = blockIdx.y;
    float acc = 0.f;
#pragma unroll
    for (int i = 0; i < 3; i++) {
        int d = threadIdx.x + i * 256;
        float s = 0.f;
        int n0 = c * 128;
        for (int n = n0; n < n0 + 128; n++)
            s += x[((size_t)b * NTOK + n) * DM + d];
        acc += s * fcw[d];
    }
    float dummy = 0.f;
    block_reduce2(acc, dummy);
    if (threadIdx.x == 0) part[b * 32 + c] = acc;
}

__global__ void final_sum_kernel(const float* __restrict__ part,
                                 const float* __restrict__ fcb,
                                 float* __restrict__ out)
{
    int t = threadIdx.x;
    int b = t >> 5, lane = t & 31;
    float v = part[b * 32 + lane];
#pragma unroll
    for (int off = 16; off > 0; off >>= 1)
        v += __shfl_down_sync(0xffffffffu, v, off);
    if (lane == 0) out[b] = v * (1.f / NTOK) + fcb[0];
}

// ---------------- driver ----------------
extern "C" void kernel_launch(void* const* d_in, const int* in_sizes, int n_in,
                              void* d_out, int out_size)
{
    const float* inputs = (const float*)d_in[0];
    const int*   rb_all = (const int*)d_in[1];
    const float* pos = (const float*)d_in[2];
    const float* tt  = (const float*)d_in[3];
    const float* eg  = (const float*)d_in[4];
    const float* eb  = (const float*)d_in[5];
    const float* Wq  = (const float*)d_in[6];  const float* bq = (const float*)d_in[7];
    const float* Wk  = (const float*)d_in[8];  const float* bk = (const float*)d_in[9];
    const float* Wv  = (const float*)d_in[10]; const float* bv = (const float*)d_in[11];
    const float* Wo  = (const float*)d_in[12]; const float* bo = (const float*)d_in[13];
    const float* l1g = (const float*)d_in[14]; const float* l1b = (const float*)d_in[15];
    const float* Wi  = (const float*)d_in[16]; const float* bi = (const float*)d_in[17];
    const float* Wd  = (const float*)d_in[18]; const float* bd = (const float*)d_in[19];
    const float* l2g = (const float*)d_in[20]; const float* l2b = (const float*)d_in[21];
    const float* fcw = (const float*)d_in[22]; const float* fcb = (const float*)d_in[23];
    float* out = (float*)d_out;

    float *x, *tb, *tb2, *a, *part, *eo, *em, *el, *bqkv, *zb;
    uint32_t *pqh, *pql, *pxh, *pxl, *pch, *pcl, *phh, *phl, *wh, *wl;
    cudaGetSymbolAddress((void**)&x,    g_x);
    cudaGetSymbolAddress((void**)&tb,   g_t);
    cudaGetSymbolAddress((void**)&tb2,  g_t2);
    cudaGetSymbolAddress((void**)&a,    g_a);
    cudaGetSymbolAddress((void**)&part, g_part);
    cudaGetSymbolAddress((void**)&eo,   g_eo);
    cudaGetSymbolAddress((void**)&em,   g_em);
    cudaGetSymbolAddress((void**)&el,   g_el);
    cudaGetSymbolAddress((void**)&bqkv, g_bqkv);
    cudaGetSymbolAddress((void**)&zb,   g_zb);
    cudaGetSymbolAddress((void**)&pqh,  g_pqh);
    cudaGetSymbolAddress((void**)&pql,  g_pql);
    cudaGetSymbolAddress((void**)&pxh,  g_pxh);
    cudaGetSymbolAddress((void**)&pxl,  g_pxl);
    cudaGetSymbolAddress((void**)&pch,  g_pch);
    cudaGetSymbolAddress((void**)&pcl,  g_pcl);
    cudaGetSymbolAddress((void**)&phh,  g_phh);
    cudaGetSymbolAddress((void**)&phl,  g_phl);
    cudaGetSymbolAddress((void**)&wh,   g_wh);
    cudaGetSymbolAddress((void**)&wl,   g_wl);

    const int ATTN_SMEM = 12800 * 4;             // 51200 bytes
    const int GEMM_SMEM = 2 * 32768;             // 65536 bytes
    cudaFuncSetAttribute((const void*)attn_mma_kernel, cudaFuncAttributeMaxDynamicSharedMemorySize, ATTN_SMEM);
    cudaFuncSetAttribute((const void*)mgemm_kernel<0, 0>, cudaFuncAttributeMaxDynamicSharedMemorySize, GEMM_SMEM);
    cudaFuncSetAttribute((const void*)mgemm_kernel<0, 1>, cudaFuncAttributeMaxDynamicSharedMemorySize, GEMM_SMEM);
    cudaFuncSetAttribute((const void*)mgemm_kernel<1, 1>, cudaFuncAttributeMaxDynamicSharedMemorySize, GEMM_SMEM);

    const int MROWS = BB * NTOK;                 // 8192
    dim3 gemm_qkv(GS / 128, MROWS / 128, 1);     // (18, 64)
    dim3 gemm_dd2(DM / 128, MROWS / 128, 2);     // (6, 64, 2) split-K
    dim3 gemm_ff(FFD / 128, MROWS / 128, 1);     // (24, 64)

    embed_ln_kernel<<<MROWS / 8, 256>>>(inputs, pos, tt, eg, eb, x, pxh, pxl);
    pack_wA_kernel<<<dim3(DM / 32, DM / 64, 8), 256>>>(Wq, Wk, Wv, Wo, wh, wl);
    pack_wB_kernel<<<dim3(FFD / 32, DM / 64, 2), 256>>>(Wi, wh, wl);
    pack_wC_kernel<<<dim3(DM / 32, FFD / 64, 2), 256>>>(Wd, wh, wl);
    concat_bias_kernel<<<18, 256>>>(bq, bk, bv, bqkv);

    for (int l = 0; l < NL; l++) {
        const uint32_t* whl = wh + (size_t)l * LOFF;
        const uint32_t* wll = wl + (size_t)l * LOFF;

        // fused QKV GEMM -> packed output
        mgemm_kernel<0, 1><<<gemm_qkv, 256, GEMM_SMEM>>>(
            pxh, pxl, whl, wll, bqkv + l * GS, nullptr, pqh, pql,
            nullptr, nullptr, KH_DD, KH_DD / 16, GS);

        // unified attention (middles + edge partials in one launch)
        attn_mma_kernel<<<dim3(NBLK - 2 + 16, NH, BB), 256, ATTN_SMEM>>>(
            pqh, pql, rb_all + l * NH * NBLK * RR, pch, pcl, eo, em, el);
        attn_edge_combine_kernel<<<dim3(2, NH, BB), 256>>>(eo, em, el, pch, pcl);

        // Wo GEMM split-K=2
        mgemm_kernel<0, 0><<<gemm_dd2, 256, GEMM_SMEM>>>(
            pch, pcl, whl + WO_OFF, wll + WO_OFF, bo + l * DM, tb, nullptr, nullptr,
            zb, tb2, KH_DD, KH_DD / 32, DM);
        ln_add3_kernel<<<MROWS / 8, 256>>>(x, tb, tb2, l1g + l * DM, l1b + l * DM, a, pxh, pxl);

        mgemm_kernel<1, 1><<<gemm_ff, 256, GEMM_SMEM>>>(
            pxh, pxl, whl + WI_OFF, wll + WI_OFF, bi + l * FFD, nullptr, phh, phl,
            nullptr, nullptr, KH_DD, KH_DD / 16, FFD);

        // Wd GEMM split-K=2
        mgemm_kernel<0, 0><<<gemm_dd2, 256, GEMM_SMEM>>>(
            phh, phl, whl + WD_OFF, wll + WD_OFF, bd + l * DM, tb, nullptr, nullptr,
            zb, tb2, KH_FF, KH_FF / 32, DM);
        ln_add3_kernel<<<MROWS / 8, 256>>>(a, tb, tb2, l2g + l * DM, l2b + l * DM, x, pxh, pxl);
    }

    final_part_kernel<<<dim3(32, BB), 256>>>(x, fcw, part);
    final_sum_kernel<<<1, 64>>>(part, fcb, out);
}